// round 1
// baseline (speedup 1.0000x reference)
#include <cuda_runtime.h>
#include <math.h>

// Problem dims (fixed by setup_inputs): B=2, S=2048, H=2048, I=8192
#define MTOK 4096          // B*S tokens
#define HDIM 2048          // hidden
#define IDIM 8192          // intermediate
#define NGU  16384         // 2*IDIM (gate+up fused weight rows)

// ---------------- scratch (static __device__ globals; no allocation) ----------------
__device__ double g_part1[4096];                         // per-block |w_gate| partial sums
__device__ double g_part2[2048];                         // per-block |w_down| partial sums
__device__ float  g_consts[4];                           // {scale1, 1/scale1, scale2, 1/scale2}
__device__ signed char g_w1q[(size_t)NGU  * HDIM];       // ternary w_gate as int8
__device__ signed char g_w2q[(size_t)HDIM * IDIM];       // ternary w_down as int8
__device__ signed char g_a1q[(size_t)MTOK * HDIM];       // int8 activations stage 1
__device__ signed char g_a2q[(size_t)MTOK * IDIM];       // int8 activations stage 2
__device__ float g_a1dq[MTOK];                           // per-token dequant (1/qscale) stage 1
__device__ float g_a2dq[MTOK];                           // per-token dequant stage 2
__device__ float g_y1[(size_t)MTOK * NGU];               // GEMM1 output (gate|up), f32

// ---------------- weight absmean: stage 1 (per-block partials, fixed slots) --------
__global__ void k_abspart(const float* __restrict__ w, int which) {
    // each block reduces exactly 8192 contiguous elements
    size_t base = (size_t)blockIdx.x * 8192 + (size_t)threadIdx.x * 4;
    double acc = 0.0;
#pragma unroll
    for (int j = 0; j < 8; j++) {
        float4 v = *reinterpret_cast<const float4*>(w + base + (size_t)j * 1024);
        acc += (double)fabsf(v.x) + (double)fabsf(v.y) +
               (double)fabsf(v.z) + (double)fabsf(v.w);
    }
    __shared__ double sm[256];
    sm[threadIdx.x] = acc;
    __syncthreads();
    for (int s = 128; s > 0; s >>= 1) {
        if (threadIdx.x < s) sm[threadIdx.x] += sm[threadIdx.x + s];
        __syncthreads();
    }
    if (threadIdx.x == 0) {
        if (which) g_part2[blockIdx.x] = sm[0];
        else       g_part1[blockIdx.x] = sm[0];
    }
}

// ---------------- weight absmean: stage 2 (single block, fixed order) --------------
__global__ void k_finalize() {
    __shared__ double sm[256];
    int t = threadIdx.x;

    double a = 0.0;
    for (int i = t; i < 4096; i += 256) a += g_part1[i];
    sm[t] = a; __syncthreads();
    for (int s = 128; s > 0; s >>= 1) { if (t < s) sm[t] += sm[t + s]; __syncthreads(); }
    double sum1 = sm[0];
    __syncthreads();

    double b = 0.0;
    for (int i = t; i < 2048; i += 256) b += g_part2[i];
    sm[t] = b; __syncthreads();
    for (int s = 128; s > 0; s >>= 1) { if (t < s) sm[t] += sm[t + s]; __syncthreads(); }

    if (t == 0) {
        float m1 = (float)(sum1 / (double)((size_t)NGU * HDIM));
        float c1 = fmaxf(m1, 1e-5f);
        float s1 = 1.0f / c1;               // weight quant scale (matches ref f32 divide)
        g_consts[0] = s1;
        g_consts[1] = 1.0f / s1;            // dequant = t / scale
        float m2 = (float)(sm[0] / (double)((size_t)HDIM * IDIM));
        float c2 = fmaxf(m2, 1e-5f);
        float s2 = 1.0f / c2;
        g_consts[2] = s2;
        g_consts[3] = 1.0f / s2;
    }
}

// ---------------- weight ternarization -> int8 -------------------------------------
__global__ void k_wquant(const float* __restrict__ w, int which, size_t n) {
    float scale = g_consts[which ? 2 : 0];
    signed char* wq = which ? g_w2q : g_w1q;
    size_t i = ((size_t)blockIdx.x * 256 + threadIdx.x) * 4;
    if (i >= n) return;
    float4 v = *reinterpret_cast<const float4*>(w + i);
    char4 o;
    o.x = (signed char)fminf(fmaxf(rintf(v.x * scale), -1.0f), 1.0f);
    o.y = (signed char)fminf(fmaxf(rintf(v.y * scale), -1.0f), 1.0f);
    o.z = (signed char)fminf(fmaxf(rintf(v.z * scale), -1.0f), 1.0f);
    o.w = (signed char)fminf(fmaxf(rintf(v.w * scale), -1.0f), 1.0f);
    *reinterpret_cast<char4*>(wq + i) = o;
}

// ---------------- stage-1: rmsnorm(x, g_gate) + per-token int8 quant ---------------
__global__ void k_actq1(const float* __restrict__ x, const float* __restrict__ g) {
    __shared__ float sm[256];
    int m = blockIdx.x, t = threadIdx.x;
    const float* xr = x + (size_t)m * HDIM;

    float v[8];
    float ss = 0.0f;
#pragma unroll
    for (int j = 0; j < 8; j++) {
        v[j] = xr[t + j * 256];
        ss += v[j] * v[j];
    }
    sm[t] = ss; __syncthreads();
    for (int s = 128; s > 0; s >>= 1) { if (t < s) sm[t] += sm[t + s]; __syncthreads(); }
    float var = sm[0] * (1.0f / (float)HDIM);
    __syncthreads();
    float r = 1.0f / sqrtf(var + 1e-8f);

    float h[8];
    float am = 0.0f;
#pragma unroll
    for (int j = 0; j < 8; j++) {
        h[j] = (v[j] * r) * g[t + j * 256];
        am = fmaxf(am, fabsf(h[j]));
    }
    sm[t] = am; __syncthreads();
    for (int s = 128; s > 0; s >>= 1) { if (t < s) sm[t] = fmaxf(sm[t], sm[t + s]); __syncthreads(); }
    float qs = 127.0f / fmaxf(sm[0], 1e-5f);

    signed char* aq = g_a1q + (size_t)m * HDIM;
#pragma unroll
    for (int j = 0; j < 8; j++) {
        float q = fminf(fmaxf(rintf(h[j] * qs), -128.0f), 127.0f);
        aq[t + j * 256] = (signed char)q;
    }
    if (t == 0) g_a1dq[m] = 1.0f / qs;
}

// ---------------- stage-2: silu(gate)*up -> rmsnorm(g_down) -> int8 quant ----------
__global__ void k_actq2(const float* __restrict__ gdown) {
    __shared__ float sm[256];
    int m = blockIdx.x, t = threadIdx.x;
    const float* yr = g_y1 + (size_t)m * NGU;

    float s[32];
    float ss = 0.0f;
#pragma unroll
    for (int j = 0; j < 32; j++) {
        int idx = t + j * 256;
        float gt = yr[idx];
        float up = yr[idx + IDIM];
        float sig = 1.0f / (1.0f + expf(-gt));
        float sv = (gt * sig) * up;
        s[j] = sv;
        ss += sv * sv;
    }
    sm[t] = ss; __syncthreads();
    for (int st = 128; st > 0; st >>= 1) { if (t < st) sm[t] += sm[t + st]; __syncthreads(); }
    float var = sm[0] * (1.0f / (float)IDIM);
    __syncthreads();
    float r = 1.0f / sqrtf(var + 1e-8f);

    float am = 0.0f;
#pragma unroll
    for (int j = 0; j < 32; j++) {
        s[j] = (s[j] * r) * gdown[t + j * 256];
        am = fmaxf(am, fabsf(s[j]));
    }
    sm[t] = am; __syncthreads();
    for (int st = 128; st > 0; st >>= 1) { if (t < st) sm[t] = fmaxf(sm[t], sm[t + st]); __syncthreads(); }
    float qs = 127.0f / fmaxf(sm[0], 1e-5f);

    signed char* aq = g_a2q + (size_t)m * IDIM;
#pragma unroll
    for (int j = 0; j < 32; j++) {
        float q = fminf(fmaxf(rintf(s[j] * qs), -128.0f), 127.0f);
        aq[t + j * 256] = (signed char)q;
    }
    if (t == 0) g_a2dq[m] = 1.0f / qs;
}

// ---------------- int8 x ternary GEMM via dp4a -------------------------------------
// C[m, n] = (sum_k A[m,k]*B[n,k]) * a_dq[m] * w_rec
// Tiles: 128x128 per block, K-step 64 bytes (16 ints). 256 threads, 8x8 microtile.
// Microtile mapping: rows ty*8+i (consecutive), cols tx + j*16 (strided) -> all
// shared loads are broadcasts (conflict-free).
__global__ __launch_bounds__(256, 2) void k_gemm(int which, float* __restrict__ outp) {
    const signed char* Ab;
    const signed char* Bb;
    const float* adq;
    float wrec;
    float* C;
    int N, Kp;
    if (which == 0) {
        Ab = g_a1q; Bb = g_w1q; adq = g_a1dq; wrec = g_consts[1];
        C = g_y1; N = NGU; Kp = HDIM / 4;
    } else {
        Ab = g_a2q; Bb = g_w2q; adq = g_a2dq; wrec = g_consts[3];
        C = outp; N = HDIM; Kp = IDIM / 4;
    }
    const int* A = reinterpret_cast<const int*>(Ab);
    const int* B = reinterpret_cast<const int*>(Bb);

    __shared__ int As[128][17];
    __shared__ int Bs[128][17];

    int t  = threadIdx.x;
    int tx = t & 15;
    int ty = t >> 4;
    int rowbase = blockIdx.y * 128;
    int colbase = blockIdx.x * 128;

    int lr = t >> 1;          // load row (0..127)
    int lc = (t & 1) * 8;     // load col start (0 or 8) in ints
    const int* Aptr = A + (size_t)(rowbase + lr) * Kp + lc;
    const int* Bptr = B + (size_t)(colbase + lr) * Kp + lc;

    int acc[8][8];
#pragma unroll
    for (int i = 0; i < 8; i++)
#pragma unroll
        for (int j = 0; j < 8; j++) acc[i][j] = 0;

    for (int kt = 0; kt < Kp; kt += 16) {
        int4 a0 = *reinterpret_cast<const int4*>(Aptr + kt);
        int4 a1 = *reinterpret_cast<const int4*>(Aptr + kt + 4);
        int4 b0 = *reinterpret_cast<const int4*>(Bptr + kt);
        int4 b1 = *reinterpret_cast<const int4*>(Bptr + kt + 4);
        As[lr][lc + 0] = a0.x; As[lr][lc + 1] = a0.y; As[lr][lc + 2] = a0.z; As[lr][lc + 3] = a0.w;
        As[lr][lc + 4] = a1.x; As[lr][lc + 5] = a1.y; As[lr][lc + 6] = a1.z; As[lr][lc + 7] = a1.w;
        Bs[lr][lc + 0] = b0.x; Bs[lr][lc + 1] = b0.y; Bs[lr][lc + 2] = b0.z; Bs[lr][lc + 3] = b0.w;
        Bs[lr][lc + 4] = b1.x; Bs[lr][lc + 5] = b1.y; Bs[lr][lc + 6] = b1.z; Bs[lr][lc + 7] = b1.w;
        __syncthreads();

#pragma unroll
        for (int kp = 0; kp < 16; kp++) {
            int ar[8], br[8];
#pragma unroll
            for (int i = 0; i < 8; i++) ar[i] = As[ty * 8 + i][kp];
#pragma unroll
            for (int j = 0; j < 8; j++) br[j] = Bs[tx + j * 16][kp];
#pragma unroll
            for (int i = 0; i < 8; i++)
#pragma unroll
                for (int j = 0; j < 8; j++)
                    acc[i][j] = __dp4a(ar[i], br[j], acc[i][j]);
        }
        __syncthreads();
    }

#pragma unroll
    for (int i = 0; i < 8; i++) {
        int row = rowbase + ty * 8 + i;
        float sc = adq[row] * wrec;
        float* Crow = C + (size_t)row * N + colbase;
#pragma unroll
        for (int j = 0; j < 8; j++)
            Crow[tx + j * 16] = (float)acc[i][j] * sc;
    }
}

// ---------------- launch ------------------------------------------------------------
extern "C" void kernel_launch(void* const* d_in, const int* in_sizes, int n_in,
                              void* d_out, int out_size) {
    const float* x      = (const float*)d_in[0];   // [2,2048,2048]
    const float* w_gate = (const float*)d_in[1];   // [16384,2048]
    const float* g_gate = (const float*)d_in[2];   // [2048]
    const float* w_down = (const float*)d_in[3];   // [2048,8192]
    const float* g_down = (const float*)d_in[4];   // [8192]
    float* out = (float*)d_out;                    // [2,2048,2048]

    // weight absmean (deterministic fp64 two-stage)
    k_abspart<<<4096, 256>>>(w_gate, 0);           // 4096 * 8192 = 33.5M
    k_abspart<<<2048, 256>>>(w_down, 1);           // 2048 * 8192 = 16.8M
    k_finalize<<<1, 256>>>();

    // weight ternarization
    k_wquant<<<(int)(((size_t)NGU * HDIM) / 1024), 256>>>(w_gate, 0, (size_t)NGU * HDIM);
    k_wquant<<<(int)(((size_t)HDIM * IDIM) / 1024), 256>>>(w_down, 1, (size_t)HDIM * IDIM);

    // stage 1: rmsnorm + activation quant
    k_actq1<<<MTOK, 256>>>(x, g_gate);

    // GEMM1: [4096,2048] x [16384,2048]^T -> g_y1 [4096,16384]
    k_gemm<<<dim3(NGU / 128, MTOK / 128), 256>>>(0, nullptr);

    // stage 2: silu(gate)*up -> rmsnorm -> quant
    k_actq2<<<MTOK, 256>>>(g_down);

    // GEMM2: [4096,8192] x [2048,8192]^T -> out [4096,2048]
    k_gemm<<<dim3(HDIM / 128, MTOK / 128), 256>>>(1, out);
}

// round 6
// speedup vs baseline: 1.6641x; 1.6641x over previous
#include <cuda_runtime.h>
#include <cuda_bf16.h>
#include <math.h>
#include <stdint.h>

// Problem dims (fixed by setup_inputs): B=2, S=2048, H=2048, I=8192
#define MTOK 4096
#define HDIM 2048
#define IDIM 8192
#define NGU  16384

// ---------------- scratch (static __device__ globals; no allocation) ----------------
// NOTE: these are referenced ONLY from device code (host-side &g_xxx is invalid!).
__device__ double g_part1[4096];
__device__ double g_part2[2048];
__device__ float  g_consts[4];                           // {s1, 1/s1, s2, 1/s2}
__device__ __nv_bfloat16 g_w1q[(size_t)NGU  * HDIM];     // ternary w_gate as bf16
__device__ __nv_bfloat16 g_w2q[(size_t)HDIM * IDIM];     // ternary w_down as bf16
__device__ __nv_bfloat16 g_a1q[(size_t)MTOK * HDIM];     // int-valued activations bf16
__device__ __nv_bfloat16 g_a2q[(size_t)MTOK * IDIM];
__device__ float g_a1dq[MTOK];
__device__ float g_a2dq[MTOK];
__device__ float g_y1[(size_t)MTOK * NGU];

#define MMAB16(c, a0, a1, a2, a3, b0, b1) \
    asm volatile("mma.sync.aligned.m16n8k16.row.col.f32.bf16.bf16.f32 " \
                 "{%0,%1,%2,%3}, {%4,%5,%6,%7}, {%8,%9}, {%0,%1,%2,%3};" \
                 : "+f"((c)[0]), "+f"((c)[1]), "+f"((c)[2]), "+f"((c)[3]) \
                 : "r"(a0), "r"(a1), "r"(a2), "r"(a3), "r"(b0), "r"(b1))

// ======================= elementwise kernels (proven) =======================
__global__ void k_abspart(const float* __restrict__ w, int which) {
    size_t base = (size_t)blockIdx.x * 8192 + (size_t)threadIdx.x * 4;
    double acc = 0.0;
#pragma unroll
    for (int j = 0; j < 8; j++) {
        float4 v = *reinterpret_cast<const float4*>(w + base + (size_t)j * 1024);
        acc += (double)fabsf(v.x) + (double)fabsf(v.y) +
               (double)fabsf(v.z) + (double)fabsf(v.w);
    }
    __shared__ double sm[256];
    sm[threadIdx.x] = acc;
    __syncthreads();
    for (int s = 128; s > 0; s >>= 1) {
        if (threadIdx.x < s) sm[threadIdx.x] += sm[threadIdx.x + s];
        __syncthreads();
    }
    if (threadIdx.x == 0) {
        if (which) g_part2[blockIdx.x] = sm[0];
        else       g_part1[blockIdx.x] = sm[0];
    }
}

__global__ void k_finalize() {
    __shared__ double sm[256];
    int t = threadIdx.x;
    double a = 0.0;
    for (int i = t; i < 4096; i += 256) a += g_part1[i];
    sm[t] = a; __syncthreads();
    for (int s = 128; s > 0; s >>= 1) { if (t < s) sm[t] += sm[t + s]; __syncthreads(); }
    double sum1 = sm[0];
    __syncthreads();
    double b = 0.0;
    for (int i = t; i < 2048; i += 256) b += g_part2[i];
    sm[t] = b; __syncthreads();
    for (int s = 128; s > 0; s >>= 1) { if (t < s) sm[t] += sm[t + s]; __syncthreads(); }
    if (t == 0) {
        float m1 = (float)(sum1 / (double)((size_t)NGU * HDIM));
        float s1 = 1.0f / fmaxf(m1, 1e-5f);
        g_consts[0] = s1; g_consts[1] = 1.0f / s1;
        float m2 = (float)(sm[0] / (double)((size_t)HDIM * IDIM));
        float s2 = 1.0f / fmaxf(m2, 1e-5f);
        g_consts[2] = s2; g_consts[3] = 1.0f / s2;
    }
}

__global__ void k_wquant(const float* __restrict__ w, int which, size_t n) {
    float scale = g_consts[which ? 2 : 0];
    __nv_bfloat16* wq = which ? g_w2q : g_w1q;       // device-side symbol use: OK
    size_t i = ((size_t)blockIdx.x * 256 + threadIdx.x) * 4;
    if (i >= n) return;
    float4 v = *reinterpret_cast<const float4*>(w + i);
    __nv_bfloat162 p0, p1;
    p0.x = __float2bfloat16(fminf(fmaxf(rintf(v.x * scale), -1.0f), 1.0f));
    p0.y = __float2bfloat16(fminf(fmaxf(rintf(v.y * scale), -1.0f), 1.0f));
    p1.x = __float2bfloat16(fminf(fmaxf(rintf(v.z * scale), -1.0f), 1.0f));
    p1.y = __float2bfloat16(fminf(fmaxf(rintf(v.w * scale), -1.0f), 1.0f));
    uint2 pk;
    pk.x = *reinterpret_cast<uint32_t*>(&p0);
    pk.y = *reinterpret_cast<uint32_t*>(&p1);
    *reinterpret_cast<uint2*>(wq + i) = pk;
}

__global__ void k_actq1(const float* __restrict__ x, const float* __restrict__ g) {
    __shared__ float sm[256];
    int m = blockIdx.x, t = threadIdx.x;
    const float* xr = x + (size_t)m * HDIM;
    float v[8]; float ss = 0.0f;
#pragma unroll
    for (int j = 0; j < 8; j++) { v[j] = xr[t + j * 256]; ss += v[j] * v[j]; }
    sm[t] = ss; __syncthreads();
    for (int s = 128; s > 0; s >>= 1) { if (t < s) sm[t] += sm[t + s]; __syncthreads(); }
    float var = sm[0] * (1.0f / (float)HDIM);
    __syncthreads();
    float r = 1.0f / sqrtf(var + 1e-8f);
    float h[8]; float am = 0.0f;
#pragma unroll
    for (int j = 0; j < 8; j++) {
        h[j] = (v[j] * r) * g[t + j * 256];
        am = fmaxf(am, fabsf(h[j]));
    }
    sm[t] = am; __syncthreads();
    for (int s = 128; s > 0; s >>= 1) { if (t < s) sm[t] = fmaxf(sm[t], sm[t + s]); __syncthreads(); }
    float qs = 127.0f / fmaxf(sm[0], 1e-5f);
    __nv_bfloat16* aq = g_a1q + (size_t)m * HDIM;
#pragma unroll
    for (int j = 0; j < 8; j++) {
        float q = fminf(fmaxf(rintf(h[j] * qs), -128.0f), 127.0f);
        aq[t + j * 256] = __float2bfloat16(q);           // exact (|int| <= 128)
    }
    if (t == 0) g_a1dq[m] = 1.0f / qs;
}

__global__ void k_actq2(const float* __restrict__ gdown) {
    __shared__ float sm[256];
    int m = blockIdx.x, t = threadIdx.x;
    const float* yr = g_y1 + (size_t)m * NGU;
    float s[32]; float ss = 0.0f;
#pragma unroll
    for (int j = 0; j < 32; j++) {
        int idx = t + j * 256;
        float gt = yr[idx];
        float up = yr[idx + IDIM];
        float sig = 1.0f / (1.0f + expf(-gt));
        float sv = (gt * sig) * up;
        s[j] = sv; ss += sv * sv;
    }
    sm[t] = ss; __syncthreads();
    for (int st = 128; st > 0; st >>= 1) { if (t < st) sm[t] += sm[t + st]; __syncthreads(); }
    float var = sm[0] * (1.0f / (float)IDIM);
    __syncthreads();
    float r = 1.0f / sqrtf(var + 1e-8f);
    float am = 0.0f;
#pragma unroll
    for (int j = 0; j < 32; j++) {
        s[j] = (s[j] * r) * gdown[t + j * 256];
        am = fmaxf(am, fabsf(s[j]));
    }
    sm[t] = am; __syncthreads();
    for (int st = 128; st > 0; st >>= 1) { if (t < st) sm[t] = fmaxf(sm[t], sm[t + st]); __syncthreads(); }
    float qs = 127.0f / fmaxf(sm[0], 1e-5f);
    __nv_bfloat16* aq = g_a2q + (size_t)m * IDIM;
#pragma unroll
    for (int j = 0; j < 32; j++) {
        float q = fminf(fmaxf(rintf(s[j] * qs), -128.0f), 127.0f);
        aq[t + j * 256] = __float2bfloat16(q);
    }
    if (t == 0) g_a2dq[m] = 1.0f / qs;
}

// ======================= bf16 HMMA GEMM (exact integer math) =======================
// C[m,n] = (sum_k A[m,k]*W[n,k]) * adq[m] * wrec
// Operand/scratch pointers selected IN DEVICE CODE via `which` (host-side
// addresses of __device__ globals are invalid — root cause of R3-R5 failures).
// CTA 128x128, 8 warps (2 M x 4 N), warp tile 64x32. K-chunk 32 elems (64B);
// 80B SMEM row pitch (conflict-free); double-buffered register-staged loads.
#define KCE 32
#define ROWB 80
#define TILE_BYTES (128 * ROWB)

__global__ __launch_bounds__(256) void k_gemm_mma(int which, float* __restrict__ outp) {
    const __nv_bfloat16* A;
    const __nv_bfloat16* W;
    const float* adq;
    float* C;
    float wrec;
    int N, K;
    if (which == 0) {
        A = g_a1q; W = g_w1q; adq = g_a1dq; C = g_y1;
        wrec = g_consts[1]; N = NGU; K = HDIM;
    } else {
        A = g_a2q; W = g_w2q; adq = g_a2dq; C = outp;
        wrec = g_consts[3]; N = HDIM; K = IDIM;
    }

    __shared__ __align__(16) char smbuf[2][2 * TILE_BYTES];

    const int tid  = threadIdx.x;
    const int lane = tid & 31;
    const int warp = tid >> 5;
    const int wm   = warp >> 2;
    const int wn   = warp & 3;
    const int g    = lane >> 2;
    const int tig  = lane & 3;
    const int rowbase = blockIdx.y * 128;
    const int colbase = blockIdx.x * 128;

    // ---- loader: 4 int4 (8 bf16 each) per thread per chunk ----
    const int pr  = tid >> 2;           // 0..63
    const int pce = (tid & 3) * 8;      // element offset 0/8/16/24
    const __nv_bfloat16* gA0 = A + (size_t)(rowbase + pr) * K + pce;
    const __nv_bfloat16* gA1 = gA0 + (size_t)64 * K;
    const __nv_bfloat16* gB0 = W + (size_t)(colbase + pr) * K + pce;
    const __nv_bfloat16* gB1 = gB0 + (size_t)64 * K;
    const uint32_t dA0 = pr * ROWB + (tid & 3) * 16;
    const uint32_t dA1 = (pr + 64) * ROWB + (tid & 3) * 16;
    const uint32_t dB0 = TILE_BYTES + pr * ROWB + (tid & 3) * 16;
    const uint32_t dB1 = TILE_BYTES + (pr + 64) * ROWB + (tid & 3) * 16;

    // ---- fragment base byte offsets (PTX m16n8k16 bf16 tables) ----
    const uint32_t abase = (uint32_t)((wm * 64 + g) * ROWB + tig * 4);
    const uint32_t bbase = (uint32_t)(TILE_BYTES + (wn * 32 + g) * ROWB + tig * 4);

    float acc[4][4][4];
#pragma unroll
    for (int i = 0; i < 4; i++)
#pragma unroll
        for (int j = 0; j < 4; j++)
#pragma unroll
            for (int q = 0; q < 4; q++) acc[i][j][q] = 0.0f;

    const int nk = K / KCE;

    // ---- prologue: stage chunk 0 ----
    {
        int4 ra = *reinterpret_cast<const int4*>(gA0);
        int4 rb = *reinterpret_cast<const int4*>(gA1);
        int4 rc = *reinterpret_cast<const int4*>(gB0);
        int4 rd = *reinterpret_cast<const int4*>(gB1);
        char* D = smbuf[0];
        *reinterpret_cast<int4*>(D + dA0) = ra;
        *reinterpret_cast<int4*>(D + dA1) = rb;
        *reinterpret_cast<int4*>(D + dB0) = rc;
        *reinterpret_cast<int4*>(D + dB1) = rd;
    }
    __syncthreads();

    for (int kt = 0; kt < nk; kt++) {
        int4 ra, rb, rc, rd;
        if (kt + 1 < nk) {
            int ko = (kt + 1) * KCE;
            ra = *reinterpret_cast<const int4*>(gA0 + ko);
            rb = *reinterpret_cast<const int4*>(gA1 + ko);
            rc = *reinterpret_cast<const int4*>(gB0 + ko);
            rd = *reinterpret_cast<const int4*>(gB1 + ko);
        }

        const char* S = smbuf[kt & 1];
#pragma unroll
        for (int kk = 0; kk < 2; kk++) {              // two k=16 sub-steps
            const uint32_t ko = kk * 32;              // 16 elems = 32 bytes
            uint32_t b0[4], b1[4];
#pragma unroll
            for (int nt = 0; nt < 4; nt++) {
                b0[nt] = *reinterpret_cast<const uint32_t*>(S + bbase + nt * 8 * ROWB + ko);
                b1[nt] = *reinterpret_cast<const uint32_t*>(S + bbase + nt * 8 * ROWB + ko + 16);
            }
#pragma unroll
            for (int mt = 0; mt < 4; mt++) {
                const uint32_t ab = abase + mt * 16 * ROWB + ko;
                uint32_t a0 = *reinterpret_cast<const uint32_t*>(S + ab);
                uint32_t a1 = *reinterpret_cast<const uint32_t*>(S + ab + 8 * ROWB);
                uint32_t a2 = *reinterpret_cast<const uint32_t*>(S + ab + 16);
                uint32_t a3 = *reinterpret_cast<const uint32_t*>(S + ab + 8 * ROWB + 16);
#pragma unroll
                for (int nt = 0; nt < 4; nt++)
                    MMAB16(acc[mt][nt], a0, a1, a2, a3, b0[nt], b1[nt]);
            }
        }
        __syncthreads();

        if (kt + 1 < nk) {
            char* D = smbuf[(kt + 1) & 1];
            *reinterpret_cast<int4*>(D + dA0) = ra;
            *reinterpret_cast<int4*>(D + dA1) = rb;
            *reinterpret_cast<int4*>(D + dB0) = rc;
            *reinterpret_cast<int4*>(D + dB1) = rd;
        }
        __syncthreads();
    }

    // ---- epilogue: rescale + store ----
#pragma unroll
    for (int mt = 0; mt < 4; mt++) {
        int row = rowbase + wm * 64 + mt * 16 + g;
        float s0 = adq[row] * wrec;
        float s1 = adq[row + 8] * wrec;
        float* cr0 = C + (size_t)row * N + colbase + wn * 32;
        float* cr1 = cr0 + (size_t)8 * N;
#pragma unroll
        for (int nt = 0; nt < 4; nt++) {
            float2 v0, v1;
            v0.x = acc[mt][nt][0] * s0;
            v0.y = acc[mt][nt][1] * s0;
            v1.x = acc[mt][nt][2] * s1;
            v1.y = acc[mt][nt][3] * s1;
            *reinterpret_cast<float2*>(cr0 + nt * 8 + tig * 2) = v0;
            *reinterpret_cast<float2*>(cr1 + nt * 8 + tig * 2) = v1;
        }
    }
}

// ======================= launch =======================
extern "C" void kernel_launch(void* const* d_in, const int* in_sizes, int n_in,
                              void* d_out, int out_size) {
    const float* x      = (const float*)d_in[0];
    const float* w_gate = (const float*)d_in[1];
    const float* g_gate = (const float*)d_in[2];
    const float* w_down = (const float*)d_in[3];
    const float* g_down = (const float*)d_in[4];
    float* out = (float*)d_out;

    // weight absmean (deterministic fp64 two-stage)
    k_abspart<<<4096, 256>>>(w_gate, 0);
    k_abspart<<<2048, 256>>>(w_down, 1);
    k_finalize<<<1, 256>>>();

    // weight ternarization -> bf16
    k_wquant<<<(int)(((size_t)NGU * HDIM) / 1024), 256>>>(w_gate, 0, (size_t)NGU * HDIM);
    k_wquant<<<(int)(((size_t)HDIM * IDIM) / 1024), 256>>>(w_down, 1, (size_t)HDIM * IDIM);

    // stage 1: rmsnorm + activation quant -> bf16
    k_actq1<<<MTOK, 256>>>(x, g_gate);

    // GEMM1: [4096,2048] x [16384,2048]^T -> g_y1 [4096,16384]
    k_gemm_mma<<<dim3(NGU / 128, MTOK / 128), 256>>>(0, nullptr);

    // stage 2: silu(gate)*up -> rmsnorm -> quant -> bf16
    k_actq2<<<MTOK, 256>>>(g_down);

    // GEMM2: [4096,8192] x [2048,8192]^T -> out [4096,2048]
    k_gemm_mma<<<dim3(HDIM / 128, MTOK / 128), 256>>>(1, out);
}

// round 7
// speedup vs baseline: 2.1649x; 1.3009x over previous
#include <cuda_runtime.h>
#include <cuda_bf16.h>
#include <math.h>
#include <stdint.h>

// Problem dims (fixed by setup_inputs): B=2, S=2048, H=2048, I=8192
#define MTOK 4096
#define HDIM 2048
#define IDIM 8192
#define NGU  16384

// ---------------- scratch (static __device__ globals; device-side use ONLY) --------
__device__ double g_part1[4096];
__device__ double g_part2[2048];
__device__ float  g_consts[4];                           // {s1, 1/s1, s2, 1/s2}
__device__ __nv_bfloat16 g_w1q[(size_t)NGU  * HDIM];
__device__ __nv_bfloat16 g_w2q[(size_t)HDIM * IDIM];
__device__ __nv_bfloat16 g_a1q[(size_t)MTOK * HDIM];
__device__ __nv_bfloat16 g_a2q[(size_t)MTOK * IDIM];
__device__ float g_a1dq[MTOK];
__device__ float g_a2dq[MTOK];
__device__ float g_y1[(size_t)MTOK * NGU];

__device__ __forceinline__ uint32_t s2u(const void* p) {
    uint32_t a;
    asm("{ .reg .u64 t; cvta.to.shared.u64 t, %1; cvt.u32.u64 %0, t; }" : "=r"(a) : "l"(p));
    return a;
}

#define MMAB16(c, a0, a1, a2, a3, b0, b1) \
    asm volatile("mma.sync.aligned.m16n8k16.row.col.f32.bf16.bf16.f32 " \
                 "{%0,%1,%2,%3}, {%4,%5,%6,%7}, {%8,%9}, {%0,%1,%2,%3};" \
                 : "+f"((c)[0]), "+f"((c)[1]), "+f"((c)[2]), "+f"((c)[3]) \
                 : "r"(a0), "r"(a1), "r"(a2), "r"(a3), "r"(b0), "r"(b1))

#define LDSM4(r, addr) \
    asm volatile("ldmatrix.sync.aligned.m8n8.x4.shared.b16 {%0,%1,%2,%3}, [%4];" \
                 : "=r"((r)[0]), "=r"((r)[1]), "=r"((r)[2]), "=r"((r)[3]) : "r"(addr))

#define CP16(dst, src) \
    asm volatile("cp.async.cg.shared.global [%0], [%1], 16;" \
                 :: "r"(dst), "l"(__cvta_generic_to_global(src)) : "memory")
#define CP_COMMIT() asm volatile("cp.async.commit_group;" ::: "memory")
#define CP_WAIT0()  asm volatile("cp.async.wait_group 0;" ::: "memory")

// ======================= elementwise kernels (proven) =======================
__global__ void k_abspart(const float* __restrict__ w, int which) {
    size_t base = (size_t)blockIdx.x * 8192 + (size_t)threadIdx.x * 4;
    double acc = 0.0;
#pragma unroll
    for (int j = 0; j < 8; j++) {
        float4 v = *reinterpret_cast<const float4*>(w + base + (size_t)j * 1024);
        acc += (double)fabsf(v.x) + (double)fabsf(v.y) +
               (double)fabsf(v.z) + (double)fabsf(v.w);
    }
    __shared__ double sm[256];
    sm[threadIdx.x] = acc;
    __syncthreads();
    for (int s = 128; s > 0; s >>= 1) {
        if (threadIdx.x < s) sm[threadIdx.x] += sm[threadIdx.x + s];
        __syncthreads();
    }
    if (threadIdx.x == 0) {
        if (which) g_part2[blockIdx.x] = sm[0];
        else       g_part1[blockIdx.x] = sm[0];
    }
}

__global__ void k_finalize() {
    __shared__ double sm[256];
    int t = threadIdx.x;
    double a = 0.0;
    for (int i = t; i < 4096; i += 256) a += g_part1[i];
    sm[t] = a; __syncthreads();
    for (int s = 128; s > 0; s >>= 1) { if (t < s) sm[t] += sm[t + s]; __syncthreads(); }
    double sum1 = sm[0];
    __syncthreads();
    double b = 0.0;
    for (int i = t; i < 2048; i += 256) b += g_part2[i];
    sm[t] = b; __syncthreads();
    for (int s = 128; s > 0; s >>= 1) { if (t < s) sm[t] += sm[t + s]; __syncthreads(); }
    if (t == 0) {
        float m1 = (float)(sum1 / (double)((size_t)NGU * HDIM));
        float s1 = 1.0f / fmaxf(m1, 1e-5f);
        g_consts[0] = s1; g_consts[1] = 1.0f / s1;
        float m2 = (float)(sm[0] / (double)((size_t)HDIM * IDIM));
        float s2 = 1.0f / fmaxf(m2, 1e-5f);
        g_consts[2] = s2; g_consts[3] = 1.0f / s2;
    }
}

// merged weight ternarization (both matrices in one launch, so GEMM1 = launch #5)
__global__ void k_wquant(const float* __restrict__ wg, const float* __restrict__ wd) {
    const unsigned NB1 = ((unsigned)NGU * HDIM) / 1024;   // 32768 blocks for w_gate
    const float* w;
    __nv_bfloat16* wq;
    float scale;
    size_t i;
    if (blockIdx.x < NB1) {
        w = wg; wq = g_w1q; scale = g_consts[0];
        i = ((size_t)blockIdx.x * 256 + threadIdx.x) * 4;
    } else {
        w = wd; wq = g_w2q; scale = g_consts[2];
        i = ((size_t)(blockIdx.x - NB1) * 256 + threadIdx.x) * 4;
    }
    float4 v = *reinterpret_cast<const float4*>(w + i);
    __nv_bfloat162 p0, p1;
    p0.x = __float2bfloat16(fminf(fmaxf(rintf(v.x * scale), -1.0f), 1.0f));
    p0.y = __float2bfloat16(fminf(fmaxf(rintf(v.y * scale), -1.0f), 1.0f));
    p1.x = __float2bfloat16(fminf(fmaxf(rintf(v.z * scale), -1.0f), 1.0f));
    p1.y = __float2bfloat16(fminf(fmaxf(rintf(v.w * scale), -1.0f), 1.0f));
    uint2 pk;
    pk.x = *reinterpret_cast<uint32_t*>(&p0);
    pk.y = *reinterpret_cast<uint32_t*>(&p1);
    *reinterpret_cast<uint2*>(wq + i) = pk;
}

__global__ void k_actq1(const float* __restrict__ x, const float* __restrict__ g) {
    __shared__ float sm[256];
    int m = blockIdx.x, t = threadIdx.x;
    const float* xr = x + (size_t)m * HDIM;
    float v[8]; float ss = 0.0f;
#pragma unroll
    for (int j = 0; j < 8; j++) { v[j] = xr[t + j * 256]; ss += v[j] * v[j]; }
    sm[t] = ss; __syncthreads();
    for (int s = 128; s > 0; s >>= 1) { if (t < s) sm[t] += sm[t + s]; __syncthreads(); }
    float var = sm[0] * (1.0f / (float)HDIM);
    __syncthreads();
    float r = 1.0f / sqrtf(var + 1e-8f);
    float h[8]; float am = 0.0f;
#pragma unroll
    for (int j = 0; j < 8; j++) {
        h[j] = (v[j] * r) * g[t + j * 256];
        am = fmaxf(am, fabsf(h[j]));
    }
    sm[t] = am; __syncthreads();
    for (int s = 128; s > 0; s >>= 1) { if (t < s) sm[t] = fmaxf(sm[t], sm[t + s]); __syncthreads(); }
    float qs = 127.0f / fmaxf(sm[0], 1e-5f);
    __nv_bfloat16* aq = g_a1q + (size_t)m * HDIM;
#pragma unroll
    for (int j = 0; j < 8; j++) {
        float q = fminf(fmaxf(rintf(h[j] * qs), -128.0f), 127.0f);
        aq[t + j * 256] = __float2bfloat16(q);
    }
    if (t == 0) g_a1dq[m] = 1.0f / qs;
}

__global__ void k_actq2(const float* __restrict__ gdown) {
    __shared__ float sm[256];
    int m = blockIdx.x, t = threadIdx.x;
    const float* yr = g_y1 + (size_t)m * NGU;
    float s[32]; float ss = 0.0f;
#pragma unroll
    for (int j = 0; j < 32; j++) {
        int idx = t + j * 256;
        float gt = yr[idx];
        float up = yr[idx + IDIM];
        float sig = 1.0f / (1.0f + expf(-gt));
        float sv = (gt * sig) * up;
        s[j] = sv; ss += sv * sv;
    }
    sm[t] = ss; __syncthreads();
    for (int st = 128; st > 0; st >>= 1) { if (t < st) sm[t] += sm[t + st]; __syncthreads(); }
    float var = sm[0] * (1.0f / (float)IDIM);
    __syncthreads();
    float r = 1.0f / sqrtf(var + 1e-8f);
    float am = 0.0f;
#pragma unroll
    for (int j = 0; j < 32; j++) {
        s[j] = (s[j] * r) * gdown[t + j * 256];
        am = fmaxf(am, fabsf(s[j]));
    }
    sm[t] = am; __syncthreads();
    for (int st = 128; st > 0; st >>= 1) { if (t < st) sm[t] = fmaxf(sm[t], sm[t + st]); __syncthreads(); }
    float qs = 127.0f / fmaxf(sm[0], 1e-5f);
    __nv_bfloat16* aq = g_a2q + (size_t)m * IDIM;
#pragma unroll
    for (int j = 0; j < 32; j++) {
        float q = fminf(fmaxf(rintf(s[j] * qs), -128.0f), 127.0f);
        aq[t + j * 256] = __float2bfloat16(q);
    }
    if (t == 0) g_a2dq[m] = 1.0f / qs;
}

// ======================= bf16 HMMA GEMM v2 =======================
// cp.async double-buffer, ONE __syncthreads per k-chunk, ldmatrix fragments.
// CTA 128x128, 8 warps (2Mx4N), warp tile 64x32. K-chunk 32 elems (64B).
// 80B SMEM pitch: conflict-free for both cp.async 16B stores and ldmatrix
// (word index 20*r mod 32 distinct for 8 consecutive rows).
#define KCE 32
#define ROWB 80
#define TILE_BYTES (128 * ROWB)
#define STAGE_BYTES (2 * TILE_BYTES)

__global__ __launch_bounds__(256) void k_gemm_mma(int which, float* __restrict__ outp) {
    const __nv_bfloat16* A;
    const __nv_bfloat16* W;
    const float* adq;
    float* C;
    float wrec;
    int N, K;
    if (which == 0) {
        A = g_a1q; W = g_w1q; adq = g_a1dq; C = g_y1;
        wrec = g_consts[1]; N = NGU; K = HDIM;
    } else {
        A = g_a2q; W = g_w2q; adq = g_a2dq; C = outp;
        wrec = g_consts[3]; N = HDIM; K = IDIM;
    }

    __shared__ __align__(16) char smbuf[2 * STAGE_BYTES];
    const uint32_t sbase = s2u(smbuf);

    const int tid  = threadIdx.x;
    const int lane = tid & 31;
    const int warp = tid >> 5;
    const int wm   = warp >> 2;
    const int wn   = warp & 3;
    const int g    = lane >> 2;
    const int tig  = lane & 3;
    const int rowbase = blockIdx.y * 128;
    const int colbase = blockIdx.x * 128;

    // ---- cp.async loader: 4 x 16B per thread per chunk ----
    const int pr  = tid >> 2;
    const int pce = (tid & 3) * 8;
    const __nv_bfloat16* gA0 = A + (size_t)(rowbase + pr) * K + pce;
    const __nv_bfloat16* gA1 = gA0 + (size_t)64 * K;
    const __nv_bfloat16* gB0 = W + (size_t)(colbase + pr) * K + pce;
    const __nv_bfloat16* gB1 = gB0 + (size_t)64 * K;
    const uint32_t dA0 = pr * ROWB + (tid & 3) * 16;
    const uint32_t dA1 = (pr + 64) * ROWB + (tid & 3) * 16;
    const uint32_t dB0 = TILE_BYTES + pr * ROWB + (tid & 3) * 16;
    const uint32_t dB1 = TILE_BYTES + (pr + 64) * ROWB + (tid & 3) * 16;

    // ---- ldmatrix lane addresses (relative to stage base) ----
    // A x4 per mt: m0/m1 = rows 0-15 k-lo, m2/m3 = rows 0-15 k-hi
    const uint32_t aL = (uint32_t)((wm * 64 + (lane & 15)) * ROWB + (lane >> 4) * 16);
    // B x4 per pair p: m0=b0[2p], m1=b1[2p], m2=b0[2p+1], m3=b1[2p+1]
    const uint32_t bL = (uint32_t)(TILE_BYTES +
        (wn * 32 + ((lane >> 4) & 1) * 8 + (lane & 7)) * ROWB + ((lane >> 3) & 1) * 16);

    float acc[4][4][4];
#pragma unroll
    for (int i = 0; i < 4; i++)
#pragma unroll
        for (int j = 0; j < 4; j++)
#pragma unroll
            for (int q = 0; q < 4; q++) acc[i][j][q] = 0.0f;

    const int nk = K / KCE;

    // ---- prologue: chunk 0 -> stage 0 ----
    CP16(sbase + dA0, gA0);
    CP16(sbase + dA1, gA1);
    CP16(sbase + dB0, gB0);
    CP16(sbase + dB1, gB1);
    CP_COMMIT();

    for (int kt = 0; kt < nk; kt++) {
        CP_WAIT0();
        __syncthreads();

        // issue next chunk into the other buffer (overlaps with compute below)
        if (kt + 1 < nk) {
            uint32_t dn = sbase + ((kt + 1) & 1) * STAGE_BYTES;
            int ko = (kt + 1) * KCE;
            CP16(dn + dA0, gA0 + ko);
            CP16(dn + dA1, gA1 + ko);
            CP16(dn + dB0, gB0 + ko);
            CP16(dn + dB1, gB1 + ko);
            CP_COMMIT();
        }

        const uint32_t so = sbase + (kt & 1) * STAGE_BYTES;
#pragma unroll
        for (int kk = 0; kk < 2; kk++) {              // two k=16 sub-steps (32B each)
            const uint32_t ko = kk * 32;
            uint32_t bf[2][4];
            LDSM4(bf[0], so + bL + ko);               // nt 0,1
            LDSM4(bf[1], so + bL + 16 * ROWB + ko);   // nt 2,3
#pragma unroll
            for (int mt = 0; mt < 4; mt++) {
                uint32_t a[4];
                LDSM4(a, so + aL + mt * 16 * ROWB + ko);
#pragma unroll
                for (int nt = 0; nt < 4; nt++) {
                    uint32_t b0 = bf[nt >> 1][(nt & 1) * 2];
                    uint32_t b1 = bf[nt >> 1][(nt & 1) * 2 + 1];
                    MMAB16(acc[mt][nt], a[0], a[1], a[2], a[3], b0, b1);
                }
            }
        }
    }

    // ---- epilogue: rescale + store ----
#pragma unroll
    for (int mt = 0; mt < 4; mt++) {
        int row = rowbase + wm * 64 + mt * 16 + g;
        float s0 = adq[row] * wrec;
        float s1 = adq[row + 8] * wrec;
        float* cr0 = C + (size_t)row * N + colbase + wn * 32;
        float* cr1 = cr0 + (size_t)8 * N;
#pragma unroll
        for (int nt = 0; nt < 4; nt++) {
            float2 v0, v1;
            v0.x = acc[mt][nt][0] * s0;
            v0.y = acc[mt][nt][1] * s0;
            v1.x = acc[mt][nt][2] * s1;
            v1.y = acc[mt][nt][3] * s1;
            *reinterpret_cast<float2*>(cr0 + nt * 8 + tig * 2) = v0;
            *reinterpret_cast<float2*>(cr1 + nt * 8 + tig * 2) = v1;
        }
    }
}

// ======================= launch =======================
extern "C" void kernel_launch(void* const* d_in, const int* in_sizes, int n_in,
                              void* d_out, int out_size) {
    const float* x      = (const float*)d_in[0];
    const float* w_gate = (const float*)d_in[1];
    const float* g_gate = (const float*)d_in[2];
    const float* w_down = (const float*)d_in[3];
    const float* g_down = (const float*)d_in[4];
    float* out = (float*)d_out;

    // launch indices: 0,1 abspart; 2 finalize; 3 wquant; 4 actq1; 5 GEMM1 (ncu -s 5)
    k_abspart<<<4096, 256>>>(w_gate, 0);
    k_abspart<<<2048, 256>>>(w_down, 1);
    k_finalize<<<1, 256>>>();
    k_wquant<<<49152, 256>>>(w_gate, w_down);
    k_actq1<<<MTOK, 256>>>(x, g_gate);
    k_gemm_mma<<<dim3(NGU / 128, MTOK / 128), 256>>>(0, nullptr);
    k_actq2<<<MTOK, 256>>>(g_down);
    k_gemm_mma<<<dim3(HDIM / 128, MTOK / 128), 256>>>(1, out);
}

// round 8
// speedup vs baseline: 2.2094x; 1.0206x over previous
#include <cuda_runtime.h>
#include <cuda_bf16.h>
#include <math.h>
#include <stdint.h>

// Problem dims (fixed by setup_inputs): B=2, S=2048, H=2048, I=8192
#define MTOK 4096
#define HDIM 2048
#define IDIM 8192
#define NGU  16384

// ---------------- scratch (static __device__ globals; device-side use ONLY) --------
__device__ double g_part1[4096];
__device__ double g_part2[2048];
__device__ float  g_consts[4];                           // {s1, 1/s1, s2, 1/s2}
__device__ __nv_bfloat16 g_w1q[(size_t)NGU  * HDIM];
__device__ __nv_bfloat16 g_w2q[(size_t)HDIM * IDIM];
__device__ __nv_bfloat16 g_a1q[(size_t)MTOK * HDIM];
__device__ __nv_bfloat16 g_a2q[(size_t)MTOK * IDIM];
__device__ float g_a1dq[MTOK];
__device__ float g_a2dq[MTOK];
__device__ float g_y1[(size_t)MTOK * NGU];

__device__ __forceinline__ uint32_t s2u(const void* p) {
    uint32_t a;
    asm("{ .reg .u64 t; cvta.to.shared.u64 t, %1; cvt.u32.u64 %0, t; }" : "=r"(a) : "l"(p));
    return a;
}

#define MMAB16(c, a0, a1, a2, a3, b0, b1) \
    asm volatile("mma.sync.aligned.m16n8k16.row.col.f32.bf16.bf16.f32 " \
                 "{%0,%1,%2,%3}, {%4,%5,%6,%7}, {%8,%9}, {%0,%1,%2,%3};" \
                 : "+f"((c)[0]), "+f"((c)[1]), "+f"((c)[2]), "+f"((c)[3]) \
                 : "r"(a0), "r"(a1), "r"(a2), "r"(a3), "r"(b0), "r"(b1))

#define LDSM4(r, addr) \
    asm volatile("ldmatrix.sync.aligned.m8n8.x4.shared.b16 {%0,%1,%2,%3}, [%4];" \
                 : "=r"((r)[0]), "=r"((r)[1]), "=r"((r)[2]), "=r"((r)[3]) : "r"(addr))

#define CP16(dst, src) \
    asm volatile("cp.async.cg.shared.global [%0], [%1], 16;" \
                 :: "r"(dst), "l"(__cvta_generic_to_global(src)) : "memory")
#define CP_COMMIT() asm volatile("cp.async.commit_group;" ::: "memory")
#define CP_WAIT2()  asm volatile("cp.async.wait_group 2;" ::: "memory")

// ======================= elementwise kernels (proven) =======================
__global__ void k_abspart(const float* __restrict__ w, int which) {
    size_t base = (size_t)blockIdx.x * 8192 + (size_t)threadIdx.x * 4;
    double acc = 0.0;
#pragma unroll
    for (int j = 0; j < 8; j++) {
        float4 v = *reinterpret_cast<const float4*>(w + base + (size_t)j * 1024);
        acc += (double)fabsf(v.x) + (double)fabsf(v.y) +
               (double)fabsf(v.z) + (double)fabsf(v.w);
    }
    __shared__ double sm[256];
    sm[threadIdx.x] = acc;
    __syncthreads();
    for (int s = 128; s > 0; s >>= 1) {
        if (threadIdx.x < s) sm[threadIdx.x] += sm[threadIdx.x + s];
        __syncthreads();
    }
    if (threadIdx.x == 0) {
        if (which) g_part2[blockIdx.x] = sm[0];
        else       g_part1[blockIdx.x] = sm[0];
    }
}

__global__ void k_finalize() {
    __shared__ double sm[256];
    int t = threadIdx.x;
    double a = 0.0;
    for (int i = t; i < 4096; i += 256) a += g_part1[i];
    sm[t] = a; __syncthreads();
    for (int s = 128; s > 0; s >>= 1) { if (t < s) sm[t] += sm[t + s]; __syncthreads(); }
    double sum1 = sm[0];
    __syncthreads();
    double b = 0.0;
    for (int i = t; i < 2048; i += 256) b += g_part2[i];
    sm[t] = b; __syncthreads();
    for (int s = 128; s > 0; s >>= 1) { if (t < s) sm[t] += sm[t + s]; __syncthreads(); }
    if (t == 0) {
        float m1 = (float)(sum1 / (double)((size_t)NGU * HDIM));
        float s1 = 1.0f / fmaxf(m1, 1e-5f);
        g_consts[0] = s1; g_consts[1] = 1.0f / s1;
        float m2 = (float)(sm[0] / (double)((size_t)HDIM * IDIM));
        float s2 = 1.0f / fmaxf(m2, 1e-5f);
        g_consts[2] = s2; g_consts[3] = 1.0f / s2;
    }
}

__global__ void k_wquant(const float* __restrict__ wg, const float* __restrict__ wd) {
    const unsigned NB1 = ((unsigned)NGU * HDIM) / 1024;
    const float* w;
    __nv_bfloat16* wq;
    float scale;
    size_t i;
    if (blockIdx.x < NB1) {
        w = wg; wq = g_w1q; scale = g_consts[0];
        i = ((size_t)blockIdx.x * 256 + threadIdx.x) * 4;
    } else {
        w = wd; wq = g_w2q; scale = g_consts[2];
        i = ((size_t)(blockIdx.x - NB1) * 256 + threadIdx.x) * 4;
    }
    float4 v = *reinterpret_cast<const float4*>(w + i);
    __nv_bfloat162 p0, p1;
    p0.x = __float2bfloat16(fminf(fmaxf(rintf(v.x * scale), -1.0f), 1.0f));
    p0.y = __float2bfloat16(fminf(fmaxf(rintf(v.y * scale), -1.0f), 1.0f));
    p1.x = __float2bfloat16(fminf(fmaxf(rintf(v.z * scale), -1.0f), 1.0f));
    p1.y = __float2bfloat16(fminf(fmaxf(rintf(v.w * scale), -1.0f), 1.0f));
    uint2 pk;
    pk.x = *reinterpret_cast<uint32_t*>(&p0);
    pk.y = *reinterpret_cast<uint32_t*>(&p1);
    *reinterpret_cast<uint2*>(wq + i) = pk;
}

__global__ void k_actq1(const float* __restrict__ x, const float* __restrict__ g) {
    __shared__ float sm[256];
    int m = blockIdx.x, t = threadIdx.x;
    const float* xr = x + (size_t)m * HDIM;
    float v[8]; float ss = 0.0f;
#pragma unroll
    for (int j = 0; j < 8; j++) { v[j] = xr[t + j * 256]; ss += v[j] * v[j]; }
    sm[t] = ss; __syncthreads();
    for (int s = 128; s > 0; s >>= 1) { if (t < s) sm[t] += sm[t + s]; __syncthreads(); }
    float var = sm[0] * (1.0f / (float)HDIM);
    __syncthreads();
    float r = 1.0f / sqrtf(var + 1e-8f);
    float h[8]; float am = 0.0f;
#pragma unroll
    for (int j = 0; j < 8; j++) {
        h[j] = (v[j] * r) * g[t + j * 256];
        am = fmaxf(am, fabsf(h[j]));
    }
    sm[t] = am; __syncthreads();
    for (int s = 128; s > 0; s >>= 1) { if (t < s) sm[t] = fmaxf(sm[t], sm[t + s]); __syncthreads(); }
    float qs = 127.0f / fmaxf(sm[0], 1e-5f);
    __nv_bfloat16* aq = g_a1q + (size_t)m * HDIM;
#pragma unroll
    for (int j = 0; j < 8; j++) {
        float q = fminf(fmaxf(rintf(h[j] * qs), -128.0f), 127.0f);
        aq[t + j * 256] = __float2bfloat16(q);
    }
    if (t == 0) g_a1dq[m] = 1.0f / qs;
}

__global__ void k_actq2(const float* __restrict__ gdown) {
    __shared__ float sm[256];
    int m = blockIdx.x, t = threadIdx.x;
    const float* yr = g_y1 + (size_t)m * NGU;
    float s[32]; float ss = 0.0f;
#pragma unroll
    for (int j = 0; j < 32; j++) {
        int idx = t + j * 256;
        float gt = yr[idx];
        float up = yr[idx + IDIM];
        float sig = 1.0f / (1.0f + expf(-gt));
        float sv = (gt * sig) * up;
        s[j] = sv; ss += sv * sv;
    }
    sm[t] = ss; __syncthreads();
    for (int st = 128; st > 0; st >>= 1) { if (t < st) sm[t] += sm[t + st]; __syncthreads(); }
    float var = sm[0] * (1.0f / (float)IDIM);
    __syncthreads();
    float r = 1.0f / sqrtf(var + 1e-8f);
    float am = 0.0f;
#pragma unroll
    for (int j = 0; j < 32; j++) {
        s[j] = (s[j] * r) * gdown[t + j * 256];
        am = fmaxf(am, fabsf(s[j]));
    }
    sm[t] = am; __syncthreads();
    for (int st = 128; st > 0; st >>= 1) { if (t < st) sm[t] = fmaxf(sm[t], sm[t + st]); __syncthreads(); }
    float qs = 127.0f / fmaxf(sm[0], 1e-5f);
    __nv_bfloat16* aq = g_a2q + (size_t)m * IDIM;
#pragma unroll
    for (int j = 0; j < 32; j++) {
        float q = fminf(fmaxf(rintf(s[j] * qs), -128.0f), 127.0f);
        aq[t + j * 256] = __float2bfloat16(q);
    }
    if (t == 0) g_a2dq[m] = 1.0f / qs;
}

// ======================= bf16 HMMA GEMM v3 =======================
// CTA tile 128(M) x 256(N), 512 threads = 16 warps (4M x 4N), warp tile 32x64.
// K-chunk 32 elems (64B); 80B pitch (proven conflict-free); 4-stage cp.async ring.
// Halves L2 operand traffic vs 128x128 tiles; 3 chunks in flight hide L2 latency.
#define KCE 32
#define ROWB 80
#define A_BYTES (128 * ROWB)               // 10240
#define STAGE_BYTES (384 * ROWB)           // A(128) + B(256) rows = 30720
#define NSTAGE 4
#define GEMM_SMEM (NSTAGE * STAGE_BYTES)   // 122880

__global__ __launch_bounds__(512) void k_gemm_mma(int which, float* __restrict__ outp) {
    const __nv_bfloat16* A;
    const __nv_bfloat16* W;
    const float* adq;
    float* C;
    float wrec;
    int N, K;
    if (which == 0) {
        A = g_a1q; W = g_w1q; adq = g_a1dq; C = g_y1;
        wrec = g_consts[1]; N = NGU; K = HDIM;
    } else {
        A = g_a2q; W = g_w2q; adq = g_a2dq; C = outp;
        wrec = g_consts[3]; N = HDIM; K = IDIM;
    }

    extern __shared__ __align__(16) char smbuf[];
    const uint32_t sbase = s2u(smbuf);

    const int tid  = threadIdx.x;
    const int lane = tid & 31;
    const int warp = tid >> 5;
    const int wm   = warp >> 2;            // 0..3 (M)
    const int wn   = warp & 3;             // 0..3 (N)
    const int g    = lane >> 2;
    const int tig  = lane & 3;
    const int rowbase = blockIdx.y * 128;
    const int colbase = blockIdx.x * 256;

    // ---- cp.async loader: 3 x 16B per thread per chunk ----
    // A: 128 rows x 4 chunks -> thread t: row t>>2, chunk t&3
    // B: 256 rows x 4 chunks -> thread t: row t>>1, chunks (t&1)*2, (t&1)*2+1
    const int ar = tid >> 2;
    const int ac = tid & 3;
    const int br = tid >> 1;
    const int bc = (tid & 1) * 2;
    const __nv_bfloat16* gA = A + (size_t)(rowbase + ar) * K + ac * 8;
    const __nv_bfloat16* gB = W + (size_t)(colbase + br) * K + bc * 8;
    const uint32_t dA = ar * ROWB + ac * 16;
    const uint32_t dB = A_BYTES + br * ROWB + bc * 16;

    // ---- ldmatrix lane addresses (same formulas as R7, wn*32 -> wn*64) ----
    const uint32_t aL = (uint32_t)((wm * 32 + (lane & 15)) * ROWB + (lane >> 4) * 16);
    const uint32_t bL = (uint32_t)(A_BYTES +
        (wn * 64 + ((lane >> 4) & 1) * 8 + (lane & 7)) * ROWB + ((lane >> 3) & 1) * 16);

    float acc[2][8][4];
#pragma unroll
    for (int i = 0; i < 2; i++)
#pragma unroll
        for (int j = 0; j < 8; j++)
#pragma unroll
            for (int q = 0; q < 4; q++) acc[i][j][q] = 0.0f;

    const int nk = K / KCE;

    // ---- prologue: stage chunks 0..2 ----
#pragma unroll
    for (int s = 0; s < 3; s++) {
        uint32_t d = sbase + s * STAGE_BYTES;
        int ko = s * KCE;
        CP16(d + dA, gA + ko);
        CP16(d + dB, gB + ko);
        CP16(d + dB + 16, gB + ko + 8);
        CP_COMMIT();
    }

    for (int kt = 0; kt < nk; kt++) {
        CP_WAIT2();                          // chunk kt arrived (<=2 groups outstanding)
        __syncthreads();

        if (kt + 3 < nk) {                   // refill slot (kt+3)%4 == (kt-1)%4
            uint32_t d = sbase + ((kt + 3) & 3) * STAGE_BYTES;
            int ko = (kt + 3) * KCE;
            CP16(d + dA, gA + ko);
            CP16(d + dB, gB + ko);
            CP16(d + dB + 16, gB + ko + 8);
        }
        CP_COMMIT();                         // commit every iter (possibly empty group)

        const uint32_t so = sbase + (kt & 3) * STAGE_BYTES;
#pragma unroll
        for (int kk = 0; kk < 2; kk++) {     // two k=16 sub-steps
            const uint32_t ko = kk * 32;
            uint32_t bf[4][4];
#pragma unroll
            for (int p = 0; p < 4; p++)      // nt pairs (0,1),(2,3),(4,5),(6,7)
                LDSM4(bf[p], so + bL + p * 16 * ROWB + ko);
#pragma unroll
            for (int mt = 0; mt < 2; mt++) {
                uint32_t a[4];
                LDSM4(a, so + aL + mt * 16 * ROWB + ko);
#pragma unroll
                for (int nt = 0; nt < 8; nt++) {
                    uint32_t b0 = bf[nt >> 1][(nt & 1) * 2];
                    uint32_t b1 = bf[nt >> 1][(nt & 1) * 2 + 1];
                    MMAB16(acc[mt][nt], a[0], a[1], a[2], a[3], b0, b1);
                }
            }
        }
    }

    // ---- epilogue: rescale + store ----
#pragma unroll
    for (int mt = 0; mt < 2; mt++) {
        int row = rowbase + wm * 32 + mt * 16 + g;
        float s0 = adq[row] * wrec;
        float s1 = adq[row + 8] * wrec;
        float* cr0 = C + (size_t)row * N + colbase + wn * 64;
        float* cr1 = cr0 + (size_t)8 * N;
#pragma unroll
        for (int nt = 0; nt < 8; nt++) {
            float2 v0, v1;
            v0.x = acc[mt][nt][0] * s0;
            v0.y = acc[mt][nt][1] * s0;
            v1.x = acc[mt][nt][2] * s1;
            v1.y = acc[mt][nt][3] * s1;
            *reinterpret_cast<float2*>(cr0 + nt * 8 + tig * 2) = v0;
            *reinterpret_cast<float2*>(cr1 + nt * 8 + tig * 2) = v1;
        }
    }
}

// ======================= launch =======================
extern "C" void kernel_launch(void* const* d_in, const int* in_sizes, int n_in,
                              void* d_out, int out_size) {
    const float* x      = (const float*)d_in[0];
    const float* w_gate = (const float*)d_in[1];
    const float* g_gate = (const float*)d_in[2];
    const float* w_down = (const float*)d_in[3];
    const float* g_down = (const float*)d_in[4];
    float* out = (float*)d_out;

    cudaFuncSetAttribute(k_gemm_mma, cudaFuncAttributeMaxDynamicSharedMemorySize, GEMM_SMEM);

    // launch indices: 0,1 abspart; 2 finalize; 3 wquant; 4 actq1; 5 GEMM1 (ncu -s 5)
    k_abspart<<<4096, 256>>>(w_gate, 0);
    k_abspart<<<2048, 256>>>(w_down, 1);
    k_finalize<<<1, 256>>>();
    k_wquant<<<49152, 256>>>(w_gate, w_down);
    k_actq1<<<MTOK, 256>>>(x, g_gate);
    k_gemm_mma<<<dim3(NGU / 256, MTOK / 128), 512, GEMM_SMEM>>>(0, nullptr);
    k_actq2<<<MTOK, 256>>>(g_down);
    k_gemm_mma<<<dim3(HDIM / 256, MTOK / 128), 512, GEMM_SMEM>>>(1, out);
}

// round 9
// speedup vs baseline: 2.3536x; 1.0653x over previous
#include <cuda_runtime.h>
#include <cuda_bf16.h>
#include <math.h>
#include <stdint.h>

// Problem dims (fixed by setup_inputs): B=2, S=2048, H=2048, I=8192
#define MTOK 4096
#define HDIM 2048
#define IDIM 8192
#define NGU  16384

// ---------------- scratch (static __device__ globals; device-side use ONLY) --------
__device__ double g_part1[4096];
__device__ double g_part2[2048];
__device__ float  g_consts[4];                           // {s1, 1/s1, s2, 1/s2}
__device__ __nv_bfloat16 g_w1q[(size_t)NGU  * HDIM];     // gate/up row-interleaved
__device__ __nv_bfloat16 g_w2q[(size_t)HDIM * IDIM];
__device__ __nv_bfloat16 g_a1q[(size_t)MTOK * HDIM];
__device__ __nv_bfloat16 g_a2q[(size_t)MTOK * IDIM];
__device__ float g_a1dq[MTOK];
__device__ float g_a2dq[MTOK];
__device__ float g_s[(size_t)MTOK * IDIM];               // silu(gate)*up, f32

__device__ __forceinline__ uint32_t s2u(const void* p) {
    uint32_t a;
    asm("{ .reg .u64 t; cvta.to.shared.u64 t, %1; cvt.u32.u64 %0, t; }" : "=r"(a) : "l"(p));
    return a;
}

#define MMAB16(c, a0, a1, a2, a3, b0, b1) \
    asm volatile("mma.sync.aligned.m16n8k16.row.col.f32.bf16.bf16.f32 " \
                 "{%0,%1,%2,%3}, {%4,%5,%6,%7}, {%8,%9}, {%0,%1,%2,%3};" \
                 : "+f"((c)[0]), "+f"((c)[1]), "+f"((c)[2]), "+f"((c)[3]) \
                 : "r"(a0), "r"(a1), "r"(a2), "r"(a3), "r"(b0), "r"(b1))

#define LDSM4(r, addr) \
    asm volatile("ldmatrix.sync.aligned.m8n8.x4.shared.b16 {%0,%1,%2,%3}, [%4];" \
                 : "=r"((r)[0]), "=r"((r)[1]), "=r"((r)[2]), "=r"((r)[3]) : "r"(addr))

#define CP16(dst, src) \
    asm volatile("cp.async.cg.shared.global [%0], [%1], 16;" \
                 :: "r"(dst), "l"(__cvta_generic_to_global(src)) : "memory")
#define CP_COMMIT() asm volatile("cp.async.commit_group;" ::: "memory")
#define CP_WAIT2()  asm volatile("cp.async.wait_group 2;" ::: "memory")

// ======================= elementwise kernels =======================
// fused: blocks [0,4096) reduce w_gate, [4096,6144) reduce w_down
__global__ void k_abspart(const float* __restrict__ wg, const float* __restrict__ wd) {
    const float* w;
    double* part;
    int bi;
    if (blockIdx.x < 4096) { w = wg; part = g_part1; bi = blockIdx.x; }
    else                   { w = wd; part = g_part2; bi = blockIdx.x - 4096; }
    size_t base = (size_t)bi * 8192 + (size_t)threadIdx.x * 4;
    double acc = 0.0;
#pragma unroll
    for (int j = 0; j < 8; j++) {
        float4 v = *reinterpret_cast<const float4*>(w + base + (size_t)j * 1024);
        acc += (double)fabsf(v.x) + (double)fabsf(v.y) +
               (double)fabsf(v.z) + (double)fabsf(v.w);
    }
    __shared__ double sm[256];
    sm[threadIdx.x] = acc;
    __syncthreads();
    for (int s = 128; s > 0; s >>= 1) {
        if (threadIdx.x < s) sm[threadIdx.x] += sm[threadIdx.x + s];
        __syncthreads();
    }
    if (threadIdx.x == 0) part[bi] = sm[0];
}

__global__ void k_finalize() {
    __shared__ double sm[256];
    int t = threadIdx.x;
    double a = 0.0;
    for (int i = t; i < 4096; i += 256) a += g_part1[i];
    sm[t] = a; __syncthreads();
    for (int s = 128; s > 0; s >>= 1) { if (t < s) sm[t] += sm[t + s]; __syncthreads(); }
    double sum1 = sm[0];
    __syncthreads();
    double b = 0.0;
    for (int i = t; i < 2048; i += 256) b += g_part2[i];
    sm[t] = b; __syncthreads();
    for (int s = 128; s > 0; s >>= 1) { if (t < s) sm[t] += sm[t + s]; __syncthreads(); }
    if (t == 0) {
        float m1 = (float)(sum1 / (double)((size_t)NGU * HDIM));
        float s1 = 1.0f / fmaxf(m1, 1e-5f);
        g_consts[0] = s1; g_consts[1] = 1.0f / s1;
        float m2 = (float)(sm[0] / (double)((size_t)HDIM * IDIM));
        float s2 = 1.0f / fmaxf(m2, 1e-5f);
        g_consts[2] = s2; g_consts[3] = 1.0f / s2;
    }
}

// weight ternarization; w_gate rows interleaved: dest row 2j=gate_j, 2j+1=up_j
__global__ void k_wquant(const float* __restrict__ wg, const float* __restrict__ wd) {
    const unsigned NB1 = ((unsigned)NGU * HDIM) / 1024;   // 32768
    const float* w;
    __nv_bfloat16* wq;
    float scale;
    size_t isrc, idst;
    if (blockIdx.x < NB1) {
        w = wg; wq = g_w1q; scale = g_consts[0];
        isrc = ((size_t)blockIdx.x * 256 + threadIdx.x) * 4;
        size_t row = isrc / HDIM;
        size_t col = isrc % HDIM;
        size_t drow = (row < IDIM) ? (2 * row) : (2 * (row - IDIM) + 1);
        idst = drow * HDIM + col;
    } else {
        w = wd; wq = g_w2q; scale = g_consts[2];
        isrc = ((size_t)(blockIdx.x - NB1) * 256 + threadIdx.x) * 4;
        idst = isrc;
    }
    float4 v = *reinterpret_cast<const float4*>(w + isrc);
    __nv_bfloat162 p0, p1;
    p0.x = __float2bfloat16(fminf(fmaxf(rintf(v.x * scale), -1.0f), 1.0f));
    p0.y = __float2bfloat16(fminf(fmaxf(rintf(v.y * scale), -1.0f), 1.0f));
    p1.x = __float2bfloat16(fminf(fmaxf(rintf(v.z * scale), -1.0f), 1.0f));
    p1.y = __float2bfloat16(fminf(fmaxf(rintf(v.w * scale), -1.0f), 1.0f));
    uint2 pk;
    pk.x = *reinterpret_cast<uint32_t*>(&p0);
    pk.y = *reinterpret_cast<uint32_t*>(&p1);
    *reinterpret_cast<uint2*>(wq + idst) = pk;
}

__global__ void k_actq1(const float* __restrict__ x, const float* __restrict__ g) {
    __shared__ float sm[256];
    int m = blockIdx.x, t = threadIdx.x;
    const float* xr = x + (size_t)m * HDIM;
    float v[8]; float ss = 0.0f;
#pragma unroll
    for (int j = 0; j < 8; j++) { v[j] = xr[t + j * 256]; ss += v[j] * v[j]; }
    sm[t] = ss; __syncthreads();
    for (int s = 128; s > 0; s >>= 1) { if (t < s) sm[t] += sm[t + s]; __syncthreads(); }
    float var = sm[0] * (1.0f / (float)HDIM);
    __syncthreads();
    float r = 1.0f / sqrtf(var + 1e-8f);
    float h[8]; float am = 0.0f;
#pragma unroll
    for (int j = 0; j < 8; j++) {
        h[j] = (v[j] * r) * g[t + j * 256];
        am = fmaxf(am, fabsf(h[j]));
    }
    sm[t] = am; __syncthreads();
    for (int s = 128; s > 0; s >>= 1) { if (t < s) sm[t] = fmaxf(sm[t], sm[t + s]); __syncthreads(); }
    float qs = 127.0f / fmaxf(sm[0], 1e-5f);
    __nv_bfloat16* aq = g_a1q + (size_t)m * HDIM;
#pragma unroll
    for (int j = 0; j < 8; j++) {
        float q = fminf(fmaxf(rintf(h[j] * qs), -128.0f), 127.0f);
        aq[t + j * 256] = __float2bfloat16(q);
    }
    if (t == 0) g_a1dq[m] = 1.0f / qs;
}

// stage-2: reads precomputed s = silu(gate)*up; rmsnorm(g_down) + int8 quant
__global__ void k_actq2(const float* __restrict__ gdown) {
    __shared__ float sm[256];
    int m = blockIdx.x, t = threadIdx.x;
    const float* sr = g_s + (size_t)m * IDIM;
    float s[32]; float ss = 0.0f;
#pragma unroll
    for (int j = 0; j < 32; j++) {
        float sv = sr[t + j * 256];
        s[j] = sv; ss += sv * sv;
    }
    sm[t] = ss; __syncthreads();
    for (int st = 128; st > 0; st >>= 1) { if (t < st) sm[t] += sm[t + st]; __syncthreads(); }
    float var = sm[0] * (1.0f / (float)IDIM);
    __syncthreads();
    float r = 1.0f / sqrtf(var + 1e-8f);
    float am = 0.0f;
#pragma unroll
    for (int j = 0; j < 32; j++) {
        s[j] = (s[j] * r) * gdown[t + j * 256];
        am = fmaxf(am, fabsf(s[j]));
    }
    sm[t] = am; __syncthreads();
    for (int st = 128; st > 0; st >>= 1) { if (t < st) sm[t] = fmaxf(sm[t], sm[t + st]); __syncthreads(); }
    float qs = 127.0f / fmaxf(sm[0], 1e-5f);
    __nv_bfloat16* aq = g_a2q + (size_t)m * IDIM;
#pragma unroll
    for (int j = 0; j < 32; j++) {
        float q = fminf(fmaxf(rintf(s[j] * qs), -128.0f), 127.0f);
        aq[t + j * 256] = __float2bfloat16(q);
    }
    if (t == 0) g_a2dq[m] = 1.0f / qs;
}

// ======================= bf16 HMMA GEMM (R8, proven; epilogue branches) =============
// At the legacy-HMMA pipe floor (rt~16/SMSP) — mainloop untouched.
// which==0: GEMM1, fused SiLU epilogue -> g_s[4096x8192] (gate/up interleaved cols)
// which==1: GEMM2 -> out
#define KCE 32
#define ROWB 80
#define A_BYTES (128 * ROWB)
#define STAGE_BYTES (384 * ROWB)
#define NSTAGE 4
#define GEMM_SMEM (NSTAGE * STAGE_BYTES)

__global__ __launch_bounds__(512) void k_gemm_mma(int which, float* __restrict__ outp) {
    const __nv_bfloat16* A;
    const __nv_bfloat16* W;
    const float* adq;
    float wrec;
    int N, K;
    if (which == 0) {
        A = g_a1q; W = g_w1q; adq = g_a1dq;
        wrec = g_consts[1]; N = NGU; K = HDIM;
    } else {
        A = g_a2q; W = g_w2q; adq = g_a2dq;
        wrec = g_consts[3]; N = HDIM; K = IDIM;
    }

    extern __shared__ __align__(16) char smbuf[];
    const uint32_t sbase = s2u(smbuf);

    const int tid  = threadIdx.x;
    const int lane = tid & 31;
    const int warp = tid >> 5;
    const int wm   = warp >> 2;
    const int wn   = warp & 3;
    const int g    = lane >> 2;
    const int tig  = lane & 3;
    const int rowbase = blockIdx.y * 128;
    const int colbase = blockIdx.x * 256;

    const int ar = tid >> 2;
    const int ac = tid & 3;
    const int br = tid >> 1;
    const int bc = (tid & 1) * 2;
    const __nv_bfloat16* gA = A + (size_t)(rowbase + ar) * K + ac * 8;
    const __nv_bfloat16* gB = W + (size_t)(colbase + br) * K + bc * 8;
    const uint32_t dA = ar * ROWB + ac * 16;
    const uint32_t dB = A_BYTES + br * ROWB + bc * 16;

    const uint32_t aL = (uint32_t)((wm * 32 + (lane & 15)) * ROWB + (lane >> 4) * 16);
    const uint32_t bL = (uint32_t)(A_BYTES +
        (wn * 64 + ((lane >> 4) & 1) * 8 + (lane & 7)) * ROWB + ((lane >> 3) & 1) * 16);

    float acc[2][8][4];
#pragma unroll
    for (int i = 0; i < 2; i++)
#pragma unroll
        for (int j = 0; j < 8; j++)
#pragma unroll
            for (int q = 0; q < 4; q++) acc[i][j][q] = 0.0f;

    const int nk = K / KCE;

#pragma unroll
    for (int s = 0; s < 3; s++) {
        uint32_t d = sbase + s * STAGE_BYTES;
        int ko = s * KCE;
        CP16(d + dA, gA + ko);
        CP16(d + dB, gB + ko);
        CP16(d + dB + 16, gB + ko + 8);
        CP_COMMIT();
    }

    for (int kt = 0; kt < nk; kt++) {
        CP_WAIT2();
        __syncthreads();

        if (kt + 3 < nk) {
            uint32_t d = sbase + ((kt + 3) & 3) * STAGE_BYTES;
            int ko = (kt + 3) * KCE;
            CP16(d + dA, gA + ko);
            CP16(d + dB, gB + ko);
            CP16(d + dB + 16, gB + ko + 8);
        }
        CP_COMMIT();

        const uint32_t so = sbase + (kt & 3) * STAGE_BYTES;
#pragma unroll
        for (int kk = 0; kk < 2; kk++) {
            const uint32_t ko = kk * 32;
            uint32_t bf[4][4];
#pragma unroll
            for (int p = 0; p < 4; p++)
                LDSM4(bf[p], so + bL + p * 16 * ROWB + ko);
#pragma unroll
            for (int mt = 0; mt < 2; mt++) {
                uint32_t a[4];
                LDSM4(a, so + aL + mt * 16 * ROWB + ko);
#pragma unroll
                for (int nt = 0; nt < 8; nt++) {
                    uint32_t b0 = bf[nt >> 1][(nt & 1) * 2];
                    uint32_t b1 = bf[nt >> 1][(nt & 1) * 2 + 1];
                    MMAB16(acc[mt][nt], a[0], a[1], a[2], a[3], b0, b1);
                }
            }
        }
    }

    // ---- epilogue ----
    if (which == 0) {
        // fused SiLU: cols interleaved (even=gate_j, odd=up_j), j = n/2
        // s[m][j] = silu(gate)*up ; identical arithmetic to the old actq2 path
#pragma unroll
        for (int mt = 0; mt < 2; mt++) {
            int row = rowbase + wm * 32 + mt * 16 + g;
            float s0 = adq[row] * wrec;
            float s1 = adq[row + 8] * wrec;
            float* sr0 = g_s + (size_t)row * IDIM + (colbase >> 1) + wn * 32;
            float* sr1 = sr0 + (size_t)8 * IDIM;
#pragma unroll
            for (int nt = 0; nt < 8; nt++) {
                float gt0 = acc[mt][nt][0] * s0;
                float up0 = acc[mt][nt][1] * s0;
                float gt1 = acc[mt][nt][2] * s1;
                float up1 = acc[mt][nt][3] * s1;
                float sg0 = 1.0f / (1.0f + expf(-gt0));
                float sg1 = 1.0f / (1.0f + expf(-gt1));
                sr0[nt * 4 + tig] = (gt0 * sg0) * up0;
                sr1[nt * 4 + tig] = (gt1 * sg1) * up1;
            }
        }
    } else {
#pragma unroll
        for (int mt = 0; mt < 2; mt++) {
            int row = rowbase + wm * 32 + mt * 16 + g;
            float s0 = adq[row] * wrec;
            float s1 = adq[row + 8] * wrec;
            float* cr0 = outp + (size_t)row * N + colbase + wn * 64;
            float* cr1 = cr0 + (size_t)8 * N;
#pragma unroll
            for (int nt = 0; nt < 8; nt++) {
                float2 v0, v1;
                v0.x = acc[mt][nt][0] * s0;
                v0.y = acc[mt][nt][1] * s0;
                v1.x = acc[mt][nt][2] * s1;
                v1.y = acc[mt][nt][3] * s1;
                *reinterpret_cast<float2*>(cr0 + nt * 8 + tig * 2) = v0;
                *reinterpret_cast<float2*>(cr1 + nt * 8 + tig * 2) = v1;
            }
        }
    }
}

// ======================= launch =======================
extern "C" void kernel_launch(void* const* d_in, const int* in_sizes, int n_in,
                              void* d_out, int out_size) {
    const float* x      = (const float*)d_in[0];
    const float* w_gate = (const float*)d_in[1];
    const float* g_gate = (const float*)d_in[2];
    const float* w_down = (const float*)d_in[3];
    const float* g_down = (const float*)d_in[4];
    float* out = (float*)d_out;

    cudaFuncSetAttribute(k_gemm_mma, cudaFuncAttributeMaxDynamicSharedMemorySize, GEMM_SMEM);

    k_abspart<<<6144, 256>>>(w_gate, w_down);
    k_finalize<<<1, 256>>>();
    k_wquant<<<49152, 256>>>(w_gate, w_down);
    k_actq1<<<MTOK, 256>>>(x, g_gate);
    k_gemm_mma<<<dim3(NGU / 256, MTOK / 128), 512, GEMM_SMEM>>>(0, nullptr);
    k_actq2<<<MTOK, 256>>>(g_down);
    k_gemm_mma<<<dim3(HDIM / 256, MTOK / 128), 512, GEMM_SMEM>>>(1, out);
}